// round 12
// baseline (speedup 1.0000x reference)
#include <cuda_runtime.h>
#include <cuda_fp16.h>
#include <cstdint>

// Problem constants
#define BATCH 16
#define NPTS  4096
#define MPTS  1024
#define C1    256
#define C2    512
#define CO    256
#define RTOT  65536
#define NZ    4
#define CHM   (MPTS / NZ)   // 256

// ---------------- scratch (static __device__ globals; no allocation) ----------
__device__ float  g_y  [(size_t)RTOT * CO];
__device__ float  g_y2 [(size_t)RTOT * CO];
__device__ float  g_Z  [(size_t)BATCH * MPTS * CO];     // P2h * W1a^T
__device__ unsigned short g_P2h[(size_t)BATCH * MPTS * 512];
__device__ unsigned short g_P1h[(size_t)RTOT * 256];
__device__ unsigned short g_A2h[(size_t)RTOT * 256];
__device__ unsigned short g_Bhi1a[CO * 512];
__device__ unsigned short g_Blo1a[CO * 512];
__device__ unsigned short g_Bhi1b[CO * 256];
__device__ unsigned short g_Blo1b[CO * 256];
__device__ unsigned short g_Bhi2 [CO * 256];
__device__ unsigned short g_Blo2 [CO * 256];
__device__ float  g_pd [(size_t)NZ * RTOT * 3];
__device__ int    g_pi [(size_t)NZ * RTOT * 3];
__device__ double g_stats[1024];

// ---------------- helpers ---------------------------------------------------------
__device__ __forceinline__ uint32_t smem_u32(const void* p) {
    uint32_t a;
    asm("{ .reg .u64 t; cvta.to.shared.u64 t, %1; cvt.u32.u64 %0, t; }" : "=r"(a) : "l"(p));
    return a;
}

__device__ __forceinline__ void cpa16(uint32_t s, const void* g) {
    asm volatile("cp.async.ca.shared.global [%0], [%1], 16;" :: "r"(s), "l"(g));
}
#define CP_COMMIT() asm volatile("cp.async.commit_group;" ::: "memory")
#define CP_WAIT0()  asm volatile("cp.async.wait_group 0;" ::: "memory")

#define LDSM4(r, addr) \
    asm volatile("ldmatrix.sync.aligned.m8n8.x4.shared.b16 {%0,%1,%2,%3}, [%4];" \
                 : "=r"((r)[0]), "=r"((r)[1]), "=r"((r)[2]), "=r"((r)[3]) : "r"(addr))

#define MMA16816(d, a, b0, b1) \
    asm volatile("mma.sync.aligned.m16n8k16.row.col.f32.f16.f16.f32 " \
                 "{%0,%1,%2,%3}, {%4,%5,%6,%7}, {%8,%9}, {%0,%1,%2,%3};" \
                 : "+f"((d)[0]), "+f"((d)[1]), "+f"((d)[2]), "+f"((d)[3]) \
                 : "r"((a)[0]), "r"((a)[1]), "r"((a)[2]), "r"((a)[3]), "r"(b0), "r"(b1))

// fp32x4 -> fp16x4 (single rounding)
__device__ __forceinline__ uint2 cvt4h(float4 v) {
    __half2 p0 = __floats2half2_rn(v.x, v.y);
    __half2 p1 = __floats2half2_rn(v.z, v.w);
    uint2 r;
    r.x = *(uint32_t*)&p0;
    r.y = *(uint32_t*)&p1;
    return r;
}

// ---------------- setup: zero stats + split W1 (a|b) + split W2 (fp16 hi/lo) ------
__global__ void setup_kernel(const float* __restrict__ W1, const float* __restrict__ W2,
                             unsigned short* __restrict__ BhiA, unsigned short* __restrict__ BloA,
                             unsigned short* __restrict__ BhiB, unsigned short* __restrict__ BloB,
                             unsigned short* __restrict__ Bhi2, unsigned short* __restrict__ Blo2,
                             double* __restrict__ stats) {
    int bid = blockIdx.x, tid = threadIdx.x;
    if (bid < 4) stats[bid * 256 + tid] = 0.0;
    if (bid < 768) {
        int idx = bid * 256 + tid;           // over 256*768
        int n = idx / 768, k = idx % 768;
        float v = W1[idx];
        __half hi = __float2half_rn(v);
        __half lo = __float2half_rn(v - __half2float(hi));
        if (k < 512) {
            BhiA[n * 512 + k] = __half_as_ushort(hi);
            BloA[n * 512 + k] = __half_as_ushort(lo);
        } else {
            BhiB[n * 256 + (k - 512)] = __half_as_ushort(hi);
            BloB[n * 256 + (k - 512)] = __half_as_ushort(lo);
        }
    } else {
        int idx = (bid - 768) * 256 + tid;   // over 256*256
        float v = W2[idx];
        __half hi = __float2half_rn(v);
        __half lo = __float2half_rn(v - __half2float(hi));
        Bhi2[idx] = __half_as_ushort(hi);
        Blo2[idx] = __half_as_ushort(lo);
    }
}

// ---------------- streaming fp32 -> fp16 convert -----------------------------------
__global__ void cvt_kernel(const float4* __restrict__ src, uint2* __restrict__ dst) {
    size_t i = (size_t)blockIdx.x * 256 + threadIdx.x;
    dst[i] = cvt4h(src[i]);
}

// ---------------- BN finalize + BN + ReLU + fp16 convert ---------------------------
__global__ void bn_cvt_kernel(const float4* __restrict__ y,
                              const double* __restrict__ stats,
                              const float* __restrict__ g, const float* __restrict__ beta,
                              uint2* __restrict__ dst) {
    __shared__ float sc[256], sh[256];
    int tid = threadIdx.x;
    {
        double mean = stats[tid] * (1.0 / RTOT);
        double var  = stats[CO + tid] * (1.0 / RTOT) - mean * mean;
        float s = g[tid] * rsqrtf((float)var + 1e-5f);
        sc[tid] = s;
        sh[tid] = beta[tid] - (float)mean * s;
    }
    __syncthreads();
    size_t i = (size_t)blockIdx.x * 256 + tid;
    float4 v = y[i];
    int c0 = (int)(i & 63) * 4;
    v.x = fmaxf(v.x * sc[c0 + 0] + sh[c0 + 0], 0.f);
    v.y = fmaxf(v.y * sc[c0 + 1] + sh[c0 + 1], 0.f);
    v.z = fmaxf(v.z * sc[c0 + 2] + sh[c0 + 2], 0.f);
    v.w = fmaxf(v.w * sc[c0 + 3] + sh[c0 + 3], 0.f);
    dst[i] = cvt4h(v);
}

// ---------------- 3-NN partials: 2 queries per thread ------------------------------
__global__ void three_nn_part_kernel(const float* __restrict__ xyz1,
                                     const float* __restrict__ xyz2,
                                     float* __restrict__ pd, int* __restrict__ pi) {
    __shared__ float sx[CHM], sy[CHM], sz[CHM], s2[CHM];
    int b = blockIdx.y, ch = blockIdx.z;
    int tid = threadIdx.x;
    const float* p2 = xyz2 + ((size_t)b * MPTS + ch * CHM) * 3;
    {
        float px = p2[tid * 3 + 0], py = p2[tid * 3 + 1], pz = p2[tid * 3 + 2];
        sx[tid] = px; sy[tid] = py; sz[tid] = pz;
        s2[tid] = px * px + py * py + pz * pz;
    }
    __syncthreads();

    int n0 = blockIdx.x * 512 + tid;
    size_t rA = (size_t)b * NPTS + n0;
    size_t rB = rA + 256;
    float ax = xyz1[rA * 3 + 0], ay = xyz1[rA * 3 + 1], az = xyz1[rA * 3 + 2];
    float bx = xyz1[rB * 3 + 0], by = xyz1[rB * 3 + 1], bz = xyz1[rB * 3 + 2];

    float a0 = 1e30f, a1 = 1e30f, a2 = 1e30f;
    int   ia0 = 0, ia1 = 0, ia2 = 0;
    float b0 = 1e30f, b1 = 1e30f, b2 = 1e30f;
    int   ib0 = 0, ib1 = 0, ib2 = 0;
    #pragma unroll 4
    for (int j = 0; j < CHM; j++) {
        float px = sx[j], py = sy[j], pz = sz[j], pp = s2[j];
        float dA = fmaf(-2.f, fmaf(ax, px, fmaf(ay, py, az * pz)), pp);
        float dB = fmaf(-2.f, fmaf(bx, px, fmaf(by, py, bz * pz)), pp);
        if (dA < a0)      { a2 = a1; ia2 = ia1; a1 = a0; ia1 = ia0; a0 = dA; ia0 = j; }
        else if (dA < a1) { a2 = a1; ia2 = ia1; a1 = dA; ia1 = j; }
        else if (dA < a2) { a2 = dA; ia2 = j; }
        if (dB < b0)      { b2 = b1; ib2 = ib1; b1 = b0; ib1 = ib0; b0 = dB; ib0 = j; }
        else if (dB < b1) { b2 = b1; ib2 = ib1; b1 = dB; ib1 = j; }
        else if (dB < b2) { b2 = dB; ib2 = j; }
    }
    int base = ch * CHM;
    size_t oA = ((size_t)ch * RTOT + rA) * 3;
    pd[oA + 0] = a0;  pd[oA + 1] = a1;  pd[oA + 2] = a2;
    pi[oA + 0] = base + ia0; pi[oA + 1] = base + ia1; pi[oA + 2] = base + ia2;
    size_t oB = ((size_t)ch * RTOT + rB) * 3;
    pd[oB + 0] = b0;  pd[oB + 1] = b1;  pd[oB + 2] = b2;
    pi[oB + 0] = base + ib0; pi[oB + 1] = base + ib1; pi[oB + 2] = base + ib2;
}

// ---------------- fp16 2-product HMMA GEMM, pre-converted A, 2 CTAs/SM -------------
// Y(M x 256) = A(M x K) * B(256 x K)^T ; A fp16 in gmem, B = W split fp16 hi+lo.
// C = Ah*Wh + Ah*Wl (2 MMAs per k16). No staging, no convert: cp.async -> ldsm -> mma.
// CTA tile 128M x 128N (N halves across CTA pairs), 8 warps (2M x 4N), warp 64x32.
#define RS 40

#define SZ_BUF   10240                // one matrix, one stage (128 * RS * 2B)
#define OFF_A    0                    // 2 stages -> 20480
#define OFF_BHI  20480                // 2 stages -> 20480
#define OFF_BLO  40960                // 2 stages -> 20480
#define OFF_IDX  61440                // 1536
#define OFF_SUM  62976                // 1024
#define OFF_SQ   64000                // 1024
#define SM_TOTAL 65024

template<int K, int GATHER, int STATS>
__global__ void __launch_bounds__(256, 2)
gemm_kernel(const unsigned short* __restrict__ Aptr,
            const unsigned short* __restrict__ BhiG,
            const unsigned short* __restrict__ BloG,
            const float* __restrict__ pd,
            const int* __restrict__ pi,
            const float* __restrict__ Z,
            float* __restrict__ Y,
            double* __restrict__ statsOut) {
    constexpr int KCH = K / 32;
    extern __shared__ char sm[];
    uint32_t sb = smem_u32(sm);

    int tid = threadIdx.x, lane = tid & 31, wid = tid >> 5;
    int wm = wid & 1, wn = wid >> 1;                  // 2M x 4N warps
    int rbase = (blockIdx.x >> 1) * 128;
    int nbase = (blockIdx.x & 1) * 128;

    const unsigned short* Bhi = BhiG + (size_t)nbase * K;
    const unsigned short* Blo = BloG + (size_t)nbase * K;
    const unsigned short* Ab = Aptr + (size_t)rbase * K;

    if (GATHER) {
        if (tid < 128) {
            int r = rbase + tid;
            float d0 = 1e30f, d1 = 1e30f, d2v = 1e30f;
            int   i0 = 0, i1 = 0, i2 = 0;
            #pragma unroll
            for (int ch = 0; ch < NZ; ch++) {
                size_t o = ((size_t)ch * RTOT + r) * 3;
                #pragma unroll
                for (int k = 0; k < 3; k++) {
                    float d = pd[o + k];
                    int   ii = pi[o + k];
                    if (d < d0)        { d2v = d1; i2 = i1; d1 = d0; i1 = i0; d0 = d; i0 = ii; }
                    else if (d < d1)   { d2v = d1; i2 = i1; d1 = d;  i1 = ii; }
                    else if (d < d2v)  { d2v = d;  i2 = ii; }
                }
            }
            int* sidx = (int*)(sm + OFF_IDX);
            sidx[tid * 3 + 0] = i0;
            sidx[tid * 3 + 1] = i1;
            sidx[tid * 3 + 2] = i2;
        }
    }
    if (STATS) {
        ((float*)(sm + OFF_SUM))[tid] = 0.f;
        ((float*)(sm + OFF_SQ))[tid]  = 0.f;
    }
    __syncthreads();

    // Per chunk: A = 512 16B slots (2/thread), B = 512 per matrix (2/thread each).
    auto cp_chunk = [&](int c, int s) {
        int k0 = c * 32;
        #pragma unroll
        for (int it = 0; it < 2; it++) {
            int slot = it * 256 + tid;
            int row = slot >> 2, q = slot & 3;
            uint32_t d = (uint32_t)(row * RS + q * 8) * 2;
            size_t go = (size_t)row * K + k0 + q * 8;
            cpa16(sb + OFF_A   + s * SZ_BUF + d, Ab  + go);
            cpa16(sb + OFF_BHI + s * SZ_BUF + d, Bhi + go);
            cpa16(sb + OFF_BLO + s * SZ_BUF + d, Blo + go);
        }
        CP_COMMIT();
    };

    cp_chunk(0, 0);
    CP_WAIT0();
    __syncthreads();

    float acc[4][4][4] = {};   // 4 m16 x 4 n8 x 4 = 64 regs

    for (int c = 0; c < KCH; c++) {
        int s = c & 1;
        if (c + 1 < KCH) cp_chunk(c + 1, 1 - s);

        uint32_t sA   = sb + OFF_A   + s * SZ_BUF;
        uint32_t sBhi = sb + OFF_BHI + s * SZ_BUF;
        uint32_t sBlo = sb + OFF_BLO + s * SZ_BUF;

        #pragma unroll
        for (int ks = 0; ks < 2; ks++) {
            int arow = wm * 64 + (lane & 15);
            int akoff = ks * 16 + (lane >> 4) * 8;
            int brow = wn * 32 + (lane & 7) + ((lane >> 4) & 1) * 8;
            int bkoff = ks * 16 + ((lane >> 3) & 1) * 8;

            uint32_t ah[4][4], bh[2][4];
            #pragma unroll
            for (int mi = 0; mi < 4; mi++)
                LDSM4(ah[mi], sA + (uint32_t)((arow + mi * 16) * RS + akoff) * 2);
            #pragma unroll
            for (int jj = 0; jj < 2; jj++)
                LDSM4(bh[jj], sBhi + (uint32_t)((brow + jj * 16) * RS + bkoff) * 2);

            // hh: Ah * Wh (16 independent MMAs)
            #pragma unroll
            for (int mi = 0; mi < 4; mi++)
                #pragma unroll
                for (int jj = 0; jj < 2; jj++) {
                    MMA16816(acc[mi][jj * 2 + 0], ah[mi], bh[jj][0], bh[jj][1]);
                    MMA16816(acc[mi][jj * 2 + 1], ah[mi], bh[jj][2], bh[jj][3]);
                }
            // hl: Ah * Wl
            uint32_t bl[2][4];
            #pragma unroll
            for (int jj = 0; jj < 2; jj++)
                LDSM4(bl[jj], sBlo + (uint32_t)((brow + jj * 16) * RS + bkoff) * 2);
            #pragma unroll
            for (int mi = 0; mi < 4; mi++)
                #pragma unroll
                for (int jj = 0; jj < 2; jj++) {
                    MMA16816(acc[mi][jj * 2 + 0], ah[mi], bl[jj][0], bl[jj][1]);
                    MMA16816(acc[mi][jj * 2 + 1], ah[mi], bl[jj][2], bl[jj][3]);
                }
        }
        if (c + 1 < KCH) CP_WAIT0();
        __syncthreads();
    }

    // ---- epilogue ----
    if (GATHER) {
        int b = rbase >> 12;
        const float* Zb = Z + (size_t)b * MPTS * CO;
        const float third = 1.0f / 3.0f;
        const int* idxsm = (const int*)(sm + OFF_IDX);
        #pragma unroll
        for (int mi = 0; mi < 4; mi++) {
            #pragma unroll
            for (int r2 = 0; r2 < 2; r2++) {
                int lrow = wm * 64 + (lane >> 2) + mi * 16 + r2 * 8;
                const int* si = idxsm + lrow * 3;
                const float* z0 = Zb + (size_t)si[0] * CO;
                const float* z1 = Zb + (size_t)si[1] * CO;
                const float* z2 = Zb + (size_t)si[2] * CO;
                #pragma unroll
                for (int nb = 0; nb < 4; nb++) {
                    int col = nbase + wn * 32 + nb * 8 + (lane & 3) * 2;
                    float2 q0 = *(const float2*)(z0 + col);
                    float2 q1 = *(const float2*)(z1 + col);
                    float2 q2 = *(const float2*)(z2 + col);
                    acc[mi][nb][r2 * 2 + 0] += (q0.x + q1.x + q2.x) * third;
                    acc[mi][nb][r2 * 2 + 1] += (q0.y + q1.y + q2.y) * third;
                }
            }
        }
    }

    int rr = rbase + wm * 64 + (lane >> 2);
    int cc0 = nbase + wn * 32 + (lane & 3) * 2;
    #pragma unroll
    for (int mi = 0; mi < 4; mi++) {
        #pragma unroll
        for (int nb = 0; nb < 4; nb++) {
            int col = cc0 + nb * 8;
            float* a = acc[mi][nb];
            *(float2*)(Y + (size_t)(rr + mi * 16)     * CO + col) = make_float2(a[0], a[1]);
            *(float2*)(Y + (size_t)(rr + mi * 16 + 8) * CO + col) = make_float2(a[2], a[3]);
        }
    }
    if (STATS) {
        float* ssum = (float*)(sm + OFF_SUM);
        float* ssq  = (float*)(sm + OFF_SQ);
        #pragma unroll
        for (int nb = 0; nb < 4; nb++) {
            int col = cc0 + nb * 8;
            float s0 = 0.f, s1 = 0.f, q0 = 0.f, q1 = 0.f;
            #pragma unroll
            for (int mi = 0; mi < 4; mi++) {
                float* a = acc[mi][nb];
                s0 += a[0] + a[2];
                s1 += a[1] + a[3];
                q0 += a[0] * a[0] + a[2] * a[2];
                q1 += a[1] * a[1] + a[3] * a[3];
            }
            atomicAdd(&ssum[col], s0);
            atomicAdd(&ssq[col],  q0);
            atomicAdd(&ssum[col + 1], s1);
            atomicAdd(&ssq[col + 1],  q1);
        }
        __syncthreads();
        if (tid < 128) {
            int col = nbase + tid;
            atomicAdd(&statsOut[col],      (double)ssum[col]);
            atomicAdd(&statsOut[CO + col], (double)ssq[col]);
        }
    }
}

// ---------------- final BN (in-block finalize) + ReLU + transpose ------------------
__global__ void bn_relu_tr_kernel(const float* __restrict__ y,
                                  const double* __restrict__ stats,
                                  const float* __restrict__ g, const float* __restrict__ beta,
                                  float* __restrict__ out) {
    __shared__ float t[32][33];
    __shared__ float sscale[32], sshift[32];
    int b = blockIdx.z;
    int n0 = blockIdx.x * 32, c0 = blockIdx.y * 32;
    if (threadIdx.y == 0) {
        int c = c0 + threadIdx.x;
        double mean = stats[c] * (1.0 / RTOT);
        double var  = stats[CO + c] * (1.0 / RTOT) - mean * mean;
        float sc = g[c] * rsqrtf((float)var + 1e-5f);
        sscale[threadIdx.x] = sc;
        sshift[threadIdx.x] = beta[c] - (float)mean * sc;
    }
    __syncthreads();
    int n = n0 + threadIdx.y, c = c0 + threadIdx.x;
    float v = y[((size_t)b * NPTS + n) * CO + c];
    v = fmaxf(v * sscale[threadIdx.x] + sshift[threadIdx.x], 0.f);
    t[threadIdx.y][threadIdx.x] = v;
    __syncthreads();
    out[((size_t)b * CO + c0 + threadIdx.y) * NPTS + n0 + threadIdx.x] = t[threadIdx.x][threadIdx.y];
}

// ---------------- launch -----------------------------------------------------------
extern "C" void kernel_launch(void* const* d_in, const int* in_sizes, int n_in,
                              void* d_out, int out_size) {
    const float* xyz1    = (const float*)d_in[0];
    const float* xyz2    = (const float*)d_in[1];
    const float* points1 = (const float*)d_in[2];
    const float* points2 = (const float*)d_in[3];
    const float* W1      = (const float*)d_in[4];
    const float* g1      = (const float*)d_in[6];
    const float* beta1   = (const float*)d_in[7];
    const float* W2      = (const float*)d_in[8];
    const float* g2      = (const float*)d_in[10];
    const float* beta2   = (const float*)d_in[11];
    float* out = (float*)d_out;

    float *y, *y2, *Z, *pd;
    unsigned short *P2h, *P1h, *A2h;
    unsigned short *Bhi1a, *Blo1a, *Bhi1b, *Blo1b, *Bhi2, *Blo2;
    int *pi;
    double* stats;
    cudaGetSymbolAddress((void**)&y, g_y);
    cudaGetSymbolAddress((void**)&y2, g_y2);
    cudaGetSymbolAddress((void**)&Z, g_Z);
    cudaGetSymbolAddress((void**)&P2h, g_P2h);
    cudaGetSymbolAddress((void**)&P1h, g_P1h);
    cudaGetSymbolAddress((void**)&A2h, g_A2h);
    cudaGetSymbolAddress((void**)&Bhi1a, g_Bhi1a);
    cudaGetSymbolAddress((void**)&Blo1a, g_Blo1a);
    cudaGetSymbolAddress((void**)&Bhi1b, g_Bhi1b);
    cudaGetSymbolAddress((void**)&Blo1b, g_Blo1b);
    cudaGetSymbolAddress((void**)&Bhi2, g_Bhi2);
    cudaGetSymbolAddress((void**)&Blo2, g_Blo2);
    cudaGetSymbolAddress((void**)&pd, g_pd);
    cudaGetSymbolAddress((void**)&pi, g_pi);
    cudaGetSymbolAddress((void**)&stats, g_stats);

    cudaFuncSetAttribute(gemm_kernel<512,0,0>, cudaFuncAttributeMaxDynamicSharedMemorySize, SM_TOTAL);
    cudaFuncSetAttribute(gemm_kernel<256,1,1>, cudaFuncAttributeMaxDynamicSharedMemorySize, SM_TOTAL);
    cudaFuncSetAttribute(gemm_kernel<256,0,1>, cudaFuncAttributeMaxDynamicSharedMemorySize, SM_TOTAL);

    // setup: zero stats + split W1/W2 into fp16 hi/lo
    setup_kernel<<<1024, 256>>>(W1, W2, Bhi1a, Blo1a, Bhi1b, Blo1b, Bhi2, Blo2, stats);

    // pre-convert A matrices to fp16
    cvt_kernel<<<(BATCH * MPTS * 512 / 4) / 256, 256>>>((const float4*)points2, (uint2*)P2h);
    cvt_kernel<<<((size_t)RTOT * 256 / 4) / 256, 256>>>((const float4*)points1, (uint2*)P1h);

    // 3-NN partials (2 queries per thread)
    three_nn_part_kernel<<<dim3(NPTS / 512, BATCH, NZ), 256>>>(xyz1, xyz2, pd, pi);

    // Z = P2h * W1a^T   (M = 16*1024, K = 512); N split across 2 CTAs
    gemm_kernel<512,0,0><<<(BATCH * MPTS / 128) * 2, 256, SM_TOTAL>>>(
        P2h, Bhi1a, Blo1a, nullptr, nullptr, nullptr, Z, nullptr);

    // Y1 = P1h * W1b^T + gather3(Z)/3 ; in-prologue NN merge; stats
    gemm_kernel<256,1,1><<<(RTOT / 128) * 2, 256, SM_TOTAL>>>(
        P1h, Bhi1b, Blo1b, pd, pi, Z, y, stats);

    // BN finalize + BN + ReLU + fp16 convert -> A2h
    bn_cvt_kernel<<<((size_t)RTOT * 256 / 4) / 256, 256>>>(
        (const float4*)y, stats, g1, beta1, (uint2*)A2h);

    // Y2 = A2h * W2^T ; stats
    gemm_kernel<256,0,1><<<(RTOT / 128) * 2, 256, SM_TOTAL>>>(
        A2h, Bhi2, Blo2, nullptr, nullptr, nullptr, y2, stats + 512);

    // final BN (in-block finalize from stats2) + ReLU + transpose
    bn_relu_tr_kernel<<<dim3(NPTS / 32, CO / 32, BATCH), dim3(32, 32)>>>(
        y2, stats + 512, g2, beta2, out);
}

// round 13
// speedup vs baseline: 1.0692x; 1.0692x over previous
#include <cuda_runtime.h>
#include <cuda_fp16.h>
#include <cstdint>

// Problem constants
#define BATCH 16
#define NPTS  4096
#define MPTS  1024
#define C1    256
#define C2    512
#define CO    256
#define RTOT  65536
#define NZ    4
#define CHM   (MPTS / NZ)   // 256

// ---------------- scratch (static __device__ globals; no allocation) ----------
__device__ float  g_y  [(size_t)RTOT * CO];
__device__ float  g_y2 [(size_t)RTOT * CO];
__device__ float  g_Z  [(size_t)BATCH * MPTS * CO];     // P2 * W1a^T
__device__ unsigned short g_Bhi1a[CO * 512];
__device__ unsigned short g_Blo1a[CO * 512];
__device__ unsigned short g_Bhi1b[CO * 256];
__device__ unsigned short g_Blo1b[CO * 256];
__device__ unsigned short g_Bhi2 [CO * 256];
__device__ unsigned short g_Blo2 [CO * 256];
__device__ float  g_pd [(size_t)NZ * RTOT * 3];
__device__ int    g_pi [(size_t)NZ * RTOT * 3];
__device__ double g_stats[1024];

// ---------------- helpers ---------------------------------------------------------
__device__ __forceinline__ uint32_t smem_u32(const void* p) {
    uint32_t a;
    asm("{ .reg .u64 t; cvta.to.shared.u64 t, %1; cvt.u32.u64 %0, t; }" : "=r"(a) : "l"(p));
    return a;
}

__device__ __forceinline__ void cpa16(uint32_t s, const void* g) {
    asm volatile("cp.async.cg.shared.global [%0], [%1], 16;" :: "r"(s), "l"(g));
}
#define CP_COMMIT() asm volatile("cp.async.commit_group;" ::: "memory")
#define CP_WAIT0()  asm volatile("cp.async.wait_group 0;" ::: "memory")

#define LDSM4(r, addr) \
    asm volatile("ldmatrix.sync.aligned.m8n8.x4.shared.b16 {%0,%1,%2,%3}, [%4];" \
                 : "=r"((r)[0]), "=r"((r)[1]), "=r"((r)[2]), "=r"((r)[3]) : "r"(addr))

#define MMA16816(d, a, b0, b1) \
    asm volatile("mma.sync.aligned.m16n8k16.row.col.f32.f16.f16.f32 " \
                 "{%0,%1,%2,%3}, {%4,%5,%6,%7}, {%8,%9}, {%0,%1,%2,%3};" \
                 : "+f"((d)[0]), "+f"((d)[1]), "+f"((d)[2]), "+f"((d)[3]) \
                 : "r"((a)[0]), "r"((a)[1]), "r"((a)[2]), "r"((a)[3]), "r"(b0), "r"(b1))

// fp32x4 -> fp16x4 (single rounding; A operand)
__device__ __forceinline__ uint2 cvt4h(float4 v) {
    __half2 p0 = __floats2half2_rn(v.x, v.y);
    __half2 p1 = __floats2half2_rn(v.z, v.w);
    uint2 r;
    r.x = *(uint32_t*)&p0;
    r.y = *(uint32_t*)&p1;
    return r;
}

// ---------------- setup: zero stats + split W1 (a|b) + split W2 (fp16 hi/lo) ------
__global__ void setup_kernel(const float* __restrict__ W1, const float* __restrict__ W2,
                             unsigned short* __restrict__ BhiA, unsigned short* __restrict__ BloA,
                             unsigned short* __restrict__ BhiB, unsigned short* __restrict__ BloB,
                             unsigned short* __restrict__ Bhi2, unsigned short* __restrict__ Blo2,
                             double* __restrict__ stats) {
    int bid = blockIdx.x, tid = threadIdx.x;
    if (bid < 4) stats[bid * 256 + tid] = 0.0;
    if (bid < 768) {
        int idx = bid * 256 + tid;           // over 256*768
        int n = idx / 768, k = idx % 768;
        float v = W1[idx];
        __half hi = __float2half_rn(v);
        __half lo = __float2half_rn(v - __half2float(hi));
        if (k < 512) {
            BhiA[n * 512 + k] = __half_as_ushort(hi);
            BloA[n * 512 + k] = __half_as_ushort(lo);
        } else {
            BhiB[n * 256 + (k - 512)] = __half_as_ushort(hi);
            BloB[n * 256 + (k - 512)] = __half_as_ushort(lo);
        }
    } else {
        int idx = (bid - 768) * 256 + tid;   // over 256*256
        float v = W2[idx];
        __half hi = __float2half_rn(v);
        __half lo = __float2half_rn(v - __half2float(hi));
        Bhi2[idx] = __half_as_ushort(hi);
        Blo2[idx] = __half_as_ushort(lo);
    }
}

// ---------------- 3-NN partials body (2 queries per thread) -----------------------
// Runs inside the fused kernel on its own CTAs; uses the dynamic smem region.
__device__ void three_nn_body(char* sm,
                              const float* __restrict__ xyz1,
                              const float* __restrict__ xyz2,
                              float* __restrict__ pd, int* __restrict__ pi,
                              int nb, int tid) {
    float* sx = (float*)sm;
    float* sy = sx + CHM;
    float* sz = sy + CHM;
    float* s2 = sz + CHM;
    int bx = nb & 7;               // NPTS/512 = 8
    int b  = (nb >> 3) & 15;       // batch
    int ch = nb >> 7;              // NZ chunk

    const float* p2 = xyz2 + ((size_t)b * MPTS + ch * CHM) * 3;
    {
        float px = p2[tid * 3 + 0], py = p2[tid * 3 + 1], pz = p2[tid * 3 + 2];
        sx[tid] = px; sy[tid] = py; sz[tid] = pz;
        s2[tid] = px * px + py * py + pz * pz;
    }
    __syncthreads();

    int n0 = bx * 512 + tid;
    size_t rA = (size_t)b * NPTS + n0;
    size_t rB = rA + 256;
    float ax = xyz1[rA * 3 + 0], ay = xyz1[rA * 3 + 1], az = xyz1[rA * 3 + 2];
    float bx2 = xyz1[rB * 3 + 0], by2 = xyz1[rB * 3 + 1], bz2 = xyz1[rB * 3 + 2];

    float a0 = 1e30f, a1 = 1e30f, a2 = 1e30f;
    int   ia0 = 0, ia1 = 0, ia2 = 0;
    float b0 = 1e30f, b1 = 1e30f, b2 = 1e30f;
    int   ib0 = 0, ib1 = 0, ib2 = 0;
    #pragma unroll 4
    for (int j = 0; j < CHM; j++) {
        float px = sx[j], py = sy[j], pz = sz[j], pp = s2[j];
        float dA = fmaf(-2.f, fmaf(ax, px, fmaf(ay, py, az * pz)), pp);
        float dB = fmaf(-2.f, fmaf(bx2, px, fmaf(by2, py, bz2 * pz)), pp);
        if (dA < a0)      { a2 = a1; ia2 = ia1; a1 = a0; ia1 = ia0; a0 = dA; ia0 = j; }
        else if (dA < a1) { a2 = a1; ia2 = ia1; a1 = dA; ia1 = j; }
        else if (dA < a2) { a2 = dA; ia2 = j; }
        if (dB < b0)      { b2 = b1; ib2 = ib1; b1 = b0; ib1 = ib0; b0 = dB; ib0 = j; }
        else if (dB < b1) { b2 = b1; ib2 = ib1; b1 = dB; ib1 = j; }
        else if (dB < b2) { b2 = dB; ib2 = j; }
    }
    int base = ch * CHM;
    size_t oA = ((size_t)ch * RTOT + rA) * 3;
    pd[oA + 0] = a0;  pd[oA + 1] = a1;  pd[oA + 2] = a2;
    pi[oA + 0] = base + ia0; pi[oA + 1] = base + ia1; pi[oA + 2] = base + ia2;
    size_t oB = ((size_t)ch * RTOT + rB) * 3;
    pd[oB + 0] = b0;  pd[oB + 1] = b1;  pd[oB + 2] = b2;
    pi[oB + 0] = base + ib0; pi[oB + 1] = base + ib1; pi[oB + 2] = base + ib2;
}

// ---------------- fp16 2-product HMMA GEMM, 2 CTAs/SM -----------------------------
// Y(M x 256) = A(M x K) * B(256 x K)^T ; A rounded once to fp16 in-kernel,
// B = W split fp16 hi+lo (exact). C = Ah*Wh + Ah*Wl  (2 MMAs per k16 step).
// CTA tile 128M x 128N (N halves across CTA pairs), 8 warps (2M x 4N), warp 64x32.
// FUSE: grid = 768; bid%3==0 -> GEMM CTA (256), else -> three_nn CTA (512).
#define RS    40
#define RSRAW 36

#define SZ_BUF   10240                // one matrix, one stage (128 * RS * 2B)
#define OFF_AHI  0                    // 2 stages -> 20480
#define OFF_BHI  20480                // 2 stages -> 20480
#define OFF_BLO  40960                // 2 stages -> 20480
#define OFF_RAW  61440                // 18432
#define OFF_IDX  79872                // 1536
#define OFF_SC   81408                // 1024
#define OFF_SH   82432                // 1024
#define OFF_SUM  83456                // 1024
#define OFF_SQ   84480                // 1024
#define SM_TOTAL 85504

template<int K, int BNFIN, int GATHER, int STATS, int FUSE>
__global__ void __launch_bounds__(256, 2)
gemm_kernel(const float* __restrict__ Aptr,
            const unsigned short* __restrict__ BhiG,
            const unsigned short* __restrict__ BloG,
            const float* __restrict__ pd,
            const int* __restrict__ pi,
            const float* __restrict__ Z,
            const double* __restrict__ statsIn,
            const float* __restrict__ gvec,
            const float* __restrict__ betavec,
            float* __restrict__ Y,
            double* __restrict__ statsOut,
            const float* __restrict__ xyz1,
            const float* __restrict__ xyz2,
            float* __restrict__ pdO,
            int* __restrict__ piO) {
    constexpr int KCH = K / 32;
    extern __shared__ char sm[];
    uint32_t sb = smem_u32(sm);

    int tid = threadIdx.x, lane = tid & 31, wid = tid >> 5;
    int bid = blockIdx.x;
    int zidx;
    if (FUSE) {
        if (bid % 3 != 0) {
            three_nn_body(sm, xyz1, xyz2, pdO, piO, bid - bid / 3 - 1, tid);
            return;
        }
        zidx = bid / 3;
    } else {
        zidx = bid;
    }

    int wm = wid & 1, wn = wid >> 1;                  // 2M x 4N warps
    int rbase = (zidx >> 1) * 128;
    int nbase = (zidx & 1) * 128;

    const unsigned short* Bhi = BhiG + (size_t)nbase * K;
    const unsigned short* Blo = BloG + (size_t)nbase * K;

    if (GATHER) {
        if (tid < 128) {
            int r = rbase + tid;
            float d0 = 1e30f, d1 = 1e30f, d2v = 1e30f;
            int   i0 = 0, i1 = 0, i2 = 0;
            #pragma unroll
            for (int ch = 0; ch < NZ; ch++) {
                size_t o = ((size_t)ch * RTOT + r) * 3;
                #pragma unroll
                for (int k = 0; k < 3; k++) {
                    float d = pd[o + k];
                    int   ii = pi[o + k];
                    if (d < d0)        { d2v = d1; i2 = i1; d1 = d0; i1 = i0; d0 = d; i0 = ii; }
                    else if (d < d1)   { d2v = d1; i2 = i1; d1 = d;  i1 = ii; }
                    else if (d < d2v)  { d2v = d;  i2 = ii; }
                }
            }
            int* sidx = (int*)(sm + OFF_IDX);
            sidx[tid * 3 + 0] = i0;
            sidx[tid * 3 + 1] = i1;
            sidx[tid * 3 + 2] = i2;
        }
    }
    if (BNFIN) {
        double mean = statsIn[tid] * (1.0 / RTOT);
        double var  = statsIn[CO + tid] * (1.0 / RTOT) - mean * mean;
        float sc = gvec[tid] * rsqrtf((float)var + 1e-5f);
        ((float*)(sm + OFF_SC))[tid] = sc;
        ((float*)(sm + OFF_SH))[tid] = betavec[tid] - (float)mean * sc;
    }
    if (STATS) {
        ((float*)(sm + OFF_SUM))[tid] = 0.f;
        ((float*)(sm + OFF_SQ))[tid]  = 0.f;
    }
    __syncthreads();

    auto cp_chunk = [&](int c, int s) {
        int k0 = c * 32;
        #pragma unroll
        for (int it = 0; it < 2; it++) {       // B: 512 16B slots per matrix
            int slot = it * 256 + tid;
            int row = slot >> 2, q = slot & 3;
            uint32_t d = (uint32_t)(row * RS + q * 8) * 2;
            size_t go = (size_t)row * K + k0 + q * 8;
            cpa16(sb + OFF_BHI + s * SZ_BUF + d, Bhi + go);
            cpa16(sb + OFF_BLO + s * SZ_BUF + d, Blo + go);
        }
        #pragma unroll
        for (int it = 0; it < 4; it++) {       // A raw fp32: 1024 16B slots
            int slot = it * 256 + tid;
            int row = slot >> 3, q = slot & 7;
            uint32_t d = sb + OFF_RAW + (uint32_t)(row * RSRAW + q * 4) * 4;
            cpa16(d, Aptr + (size_t)(rbase + row) * K + k0 + q * 4);
        }
        CP_COMMIT();
    };

    auto convert_chunk = [&](int c, int s) {
        int k0 = c * 32;
        #pragma unroll
        for (int it = 0; it < 4; it++) {
            int slot = it * 256 + tid;
            int row = slot >> 3, q = slot & 7;
            float4 v = *(const float4*)(sm + OFF_RAW + (uint32_t)(row * RSRAW + q * 4) * 4);
            if (BNFIN) {
                const float* sc = (const float*)(sm + OFF_SC) + k0 + q * 4;
                const float* sh = (const float*)(sm + OFF_SH) + k0 + q * 4;
                v.x = fmaxf(v.x * sc[0] + sh[0], 0.f);
                v.y = fmaxf(v.y * sc[1] + sh[1], 0.f);
                v.z = fmaxf(v.z * sc[2] + sh[2], 0.f);
                v.w = fmaxf(v.w * sc[3] + sh[3], 0.f);
            }
            uint2 h = cvt4h(v);
            *(uint2*)(sm + OFF_AHI + s * SZ_BUF + (uint32_t)(row * RS + q * 4) * 2) = h;
        }
    };

    cp_chunk(0, 0);
    CP_WAIT0();
    convert_chunk(0, 0);
    __syncthreads();

    float acc[4][4][4] = {};   // 4 m16 x 4 n8 x 4 = 64 regs

    for (int c = 0; c < KCH; c++) {
        int s = c & 1;
        if (c + 1 < KCH) cp_chunk(c + 1, 1 - s);

        uint32_t sAhi = sb + OFF_AHI + s * SZ_BUF;
        uint32_t sBhi = sb + OFF_BHI + s * SZ_BUF;
        uint32_t sBlo = sb + OFF_BLO + s * SZ_BUF;

        #pragma unroll
        for (int ks = 0; ks < 2; ks++) {
            int arow = wm * 64 + (lane & 15);
            int akoff = ks * 16 + (lane >> 4) * 8;
            int brow = wn * 32 + (lane & 7) + ((lane >> 4) & 1) * 8;
            int bkoff = ks * 16 + ((lane >> 3) & 1) * 8;

            uint32_t ah[4][4], bh[2][4];
            #pragma unroll
            for (int mi = 0; mi < 4; mi++)
                LDSM4(ah[mi], sAhi + (uint32_t)((arow + mi * 16) * RS + akoff) * 2);
            #pragma unroll
            for (int jj = 0; jj < 2; jj++)
                LDSM4(bh[jj], sBhi + (uint32_t)((brow + jj * 16) * RS + bkoff) * 2);

            // hh: Ah * Wh (16 independent MMAs)
            #pragma unroll
            for (int mi = 0; mi < 4; mi++)
                #pragma unroll
                for (int jj = 0; jj < 2; jj++) {
                    MMA16816(acc[mi][jj * 2 + 0], ah[mi], bh[jj][0], bh[jj][1]);
                    MMA16816(acc[mi][jj * 2 + 1], ah[mi], bh[jj][2], bh[jj][3]);
                }
            // hl: Ah * Wl
            uint32_t bl[2][4];
            #pragma unroll
            for (int jj = 0; jj < 2; jj++)
                LDSM4(bl[jj], sBlo + (uint32_t)((brow + jj * 16) * RS + bkoff) * 2);
            #pragma unroll
            for (int mi = 0; mi < 4; mi++)
                #pragma unroll
                for (int jj = 0; jj < 2; jj++) {
                    MMA16816(acc[mi][jj * 2 + 0], ah[mi], bl[jj][0], bl[jj][1]);
                    MMA16816(acc[mi][jj * 2 + 1], ah[mi], bl[jj][2], bl[jj][3]);
                }
        }
        if (c + 1 < KCH) {
            CP_WAIT0();
            convert_chunk(c + 1, 1 - s);
        }
        __syncthreads();
    }

    // ---- epilogue ----
    if (GATHER) {
        int b = rbase >> 12;
        const float* Zb = Z + (size_t)b * MPTS * CO;
        const float third = 1.0f / 3.0f;
        const int* idxsm = (const int*)(sm + OFF_IDX);
        #pragma unroll
        for (int mi = 0; mi < 4; mi++) {
            #pragma unroll
            for (int r2 = 0; r2 < 2; r2++) {
                int lrow = wm * 64 + (lane >> 2) + mi * 16 + r2 * 8;
                const int* si = idxsm + lrow * 3;
                const float* z0 = Zb + (size_t)si[0] * CO;
                const float* z1 = Zb + (size_t)si[1] * CO;
                const float* z2 = Zb + (size_t)si[2] * CO;
                #pragma unroll
                for (int nb = 0; nb < 4; nb++) {
                    int col = nbase + wn * 32 + nb * 8 + (lane & 3) * 2;
                    float2 q0 = *(const float2*)(z0 + col);
                    float2 q1 = *(const float2*)(z1 + col);
                    float2 q2 = *(const float2*)(z2 + col);
                    acc[mi][nb][r2 * 2 + 0] += (q0.x + q1.x + q2.x) * third;
                    acc[mi][nb][r2 * 2 + 1] += (q0.y + q1.y + q2.y) * third;
                }
            }
        }
    }

    int rr = rbase + wm * 64 + (lane >> 2);
    int cc0 = nbase + wn * 32 + (lane & 3) * 2;
    #pragma unroll
    for (int mi = 0; mi < 4; mi++) {
        #pragma unroll
        for (int nb = 0; nb < 4; nb++) {
            int col = cc0 + nb * 8;
            float* a = acc[mi][nb];
            *(float2*)(Y + (size_t)(rr + mi * 16)     * CO + col) = make_float2(a[0], a[1]);
            *(float2*)(Y + (size_t)(rr + mi * 16 + 8) * CO + col) = make_float2(a[2], a[3]);
        }
    }
    if (STATS) {
        float* ssum = (float*)(sm + OFF_SUM);
        float* ssq  = (float*)(sm + OFF_SQ);
        #pragma unroll
        for (int nb = 0; nb < 4; nb++) {
            int col = cc0 + nb * 8;
            float s0 = 0.f, s1 = 0.f, q0 = 0.f, q1 = 0.f;
            #pragma unroll
            for (int mi = 0; mi < 4; mi++) {
                float* a = acc[mi][nb];
                s0 += a[0] + a[2];
                s1 += a[1] + a[3];
                q0 += a[0] * a[0] + a[2] * a[2];
                q1 += a[1] * a[1] + a[3] * a[3];
            }
            atomicAdd(&ssum[col], s0);
            atomicAdd(&ssq[col],  q0);
            atomicAdd(&ssum[col + 1], s1);
            atomicAdd(&ssq[col + 1],  q1);
        }
        __syncthreads();
        if (tid < 128) {
            int col = nbase + tid;
            atomicAdd(&statsOut[col],      (double)ssum[col]);
            atomicAdd(&statsOut[CO + col], (double)ssq[col]);
        }
    }
}

// ---------------- final BN (in-block finalize) + ReLU + transpose ------------------
__global__ void bn_relu_tr_kernel(const float* __restrict__ y,
                                  const double* __restrict__ stats,
                                  const float* __restrict__ g, const float* __restrict__ beta,
                                  float* __restrict__ out) {
    __shared__ float t[32][33];
    __shared__ float sscale[32], sshift[32];
    int b = blockIdx.z;
    int n0 = blockIdx.x * 32, c0 = blockIdx.y * 32;
    if (threadIdx.y == 0) {
        int c = c0 + threadIdx.x;
        double mean = stats[c] * (1.0 / RTOT);
        double var  = stats[CO + c] * (1.0 / RTOT) - mean * mean;
        float sc = g[c] * rsqrtf((float)var + 1e-5f);
        sscale[threadIdx.x] = sc;
        sshift[threadIdx.x] = beta[c] - (float)mean * sc;
    }
    __syncthreads();
    int n = n0 + threadIdx.y, c = c0 + threadIdx.x;
    float v = y[((size_t)b * NPTS + n) * CO + c];
    v = fmaxf(v * sscale[threadIdx.x] + sshift[threadIdx.x], 0.f);
    t[threadIdx.y][threadIdx.x] = v;
    __syncthreads();
    out[((size_t)b * CO + c0 + threadIdx.y) * NPTS + n0 + threadIdx.x] = t[threadIdx.x][threadIdx.y];
}

// ---------------- launch -----------------------------------------------------------
extern "C" void kernel_launch(void* const* d_in, const int* in_sizes, int n_in,
                              void* d_out, int out_size) {
    const float* xyz1    = (const float*)d_in[0];
    const float* xyz2    = (const float*)d_in[1];
    const float* points1 = (const float*)d_in[2];
    const float* points2 = (const float*)d_in[3];
    const float* W1      = (const float*)d_in[4];
    const float* g1      = (const float*)d_in[6];
    const float* beta1   = (const float*)d_in[7];
    const float* W2      = (const float*)d_in[8];
    const float* g2      = (const float*)d_in[10];
    const float* beta2   = (const float*)d_in[11];
    float* out = (float*)d_out;

    float *y, *y2, *Z, *pd;
    unsigned short *Bhi1a, *Blo1a, *Bhi1b, *Blo1b, *Bhi2, *Blo2;
    int *pi;
    double* stats;
    cudaGetSymbolAddress((void**)&y, g_y);
    cudaGetSymbolAddress((void**)&y2, g_y2);
    cudaGetSymbolAddress((void**)&Z, g_Z);
    cudaGetSymbolAddress((void**)&Bhi1a, g_Bhi1a);
    cudaGetSymbolAddress((void**)&Blo1a, g_Blo1a);
    cudaGetSymbolAddress((void**)&Bhi1b, g_Bhi1b);
    cudaGetSymbolAddress((void**)&Blo1b, g_Blo1b);
    cudaGetSymbolAddress((void**)&Bhi2, g_Bhi2);
    cudaGetSymbolAddress((void**)&Blo2, g_Blo2);
    cudaGetSymbolAddress((void**)&pd, g_pd);
    cudaGetSymbolAddress((void**)&pi, g_pi);
    cudaGetSymbolAddress((void**)&stats, g_stats);

    cudaFuncSetAttribute(gemm_kernel<512,0,0,0,1>, cudaFuncAttributeMaxDynamicSharedMemorySize, SM_TOTAL);
    cudaFuncSetAttribute(gemm_kernel<256,0,1,1,0>, cudaFuncAttributeMaxDynamicSharedMemorySize, SM_TOTAL);
    cudaFuncSetAttribute(gemm_kernel<256,1,0,1,0>, cudaFuncAttributeMaxDynamicSharedMemorySize, SM_TOTAL);

    // setup: zero stats + split W1/W2 into fp16 hi/lo
    setup_kernel<<<1024, 256>>>(W1, W2, Bhi1a, Blo1a, Bhi1b, Blo1b, Bhi2, Blo2, stats);

    // FUSED: Z = points2 * W1a^T  (256 GEMM CTAs) + 3-NN partials (512 CTAs),
    // interleaved bid%3 so most SMs co-host one tensor-bound and one ALU-bound CTA.
    gemm_kernel<512,0,0,0,1><<<768, 256, SM_TOTAL>>>(
        points2, Bhi1a, Blo1a, nullptr, nullptr, nullptr, nullptr, nullptr, nullptr,
        Z, nullptr, xyz1, xyz2, pd, pi);

    // Y1 = points1 * W1b^T + gather3(Z)/3 ; in-prologue NN merge; stats
    gemm_kernel<256,0,1,1,0><<<(RTOT / 128) * 2, 256, SM_TOTAL>>>(
        points1, Bhi1b, Blo1b, pd, pi, Z, nullptr, nullptr, nullptr, y, stats,
        nullptr, nullptr, nullptr, nullptr);

    // Y2 = relu(bn(Y1)) * W2^T ; in-prologue finalize from stats1 ; stats
    gemm_kernel<256,1,0,1,0><<<(RTOT / 128) * 2, 256, SM_TOTAL>>>(
        y, Bhi2, Blo2, nullptr, nullptr, nullptr, stats, g1, beta1, y2, stats + 512,
        nullptr, nullptr, nullptr, nullptr);

    // final BN (in-block finalize from stats2) + ReLU + transpose
    bn_relu_tr_kernel<<<dim3(NPTS / 32, CO / 32, BATCH), dim3(32, 32)>>>(
        y2, stats + 512, g2, beta2, out);
}

// round 14
// speedup vs baseline: 1.1590x; 1.0839x over previous
#include <cuda_runtime.h>
#include <cuda_fp16.h>
#include <cstdint>

// Problem constants
#define BATCH 16
#define NPTS  4096
#define MPTS  1024
#define C1    256
#define C2    512
#define CO    256
#define RTOT  65536
#define NZ    4
#define CHM   (MPTS / NZ)   // 256

// ---------------- scratch (static __device__ globals; no allocation) ----------
__device__ float  g_y  [(size_t)RTOT * CO];
__device__ float  g_y2 [(size_t)RTOT * CO];
__device__ float  g_Z  [(size_t)BATCH * MPTS * CO];     // P2 * W1a^T
__device__ unsigned short g_Bh1a[CO * 512];
__device__ unsigned short g_Bh1b[CO * 256];
__device__ unsigned short g_Bh2 [CO * 256];
__device__ float  g_pd [(size_t)NZ * RTOT * 3];
__device__ int    g_pi [(size_t)NZ * RTOT * 3];
__device__ double g_stats[1024];

// ---------------- helpers ---------------------------------------------------------
__device__ __forceinline__ uint32_t smem_u32(const void* p) {
    uint32_t a;
    asm("{ .reg .u64 t; cvta.to.shared.u64 t, %1; cvt.u32.u64 %0, t; }" : "=r"(a) : "l"(p));
    return a;
}

__device__ __forceinline__ void cpa16(uint32_t s, const void* g) {
    asm volatile("cp.async.cg.shared.global [%0], [%1], 16;" :: "r"(s), "l"(g));
}
#define CP_COMMIT() asm volatile("cp.async.commit_group;" ::: "memory")
#define CP_WAIT0()  asm volatile("cp.async.wait_group 0;" ::: "memory")

#define LDSM4(r, addr) \
    asm volatile("ldmatrix.sync.aligned.m8n8.x4.shared.b16 {%0,%1,%2,%3}, [%4];" \
                 : "=r"((r)[0]), "=r"((r)[1]), "=r"((r)[2]), "=r"((r)[3]) : "r"(addr))

#define MMA16816(d, a, b0, b1) \
    asm volatile("mma.sync.aligned.m16n8k16.row.col.f32.f16.f16.f32 " \
                 "{%0,%1,%2,%3}, {%4,%5,%6,%7}, {%8,%9}, {%0,%1,%2,%3};" \
                 : "+f"((d)[0]), "+f"((d)[1]), "+f"((d)[2]), "+f"((d)[3]) \
                 : "r"((a)[0]), "r"((a)[1]), "r"((a)[2]), "r"((a)[3]), "r"(b0), "r"(b1))

// fp32x4 -> fp16x4 (single rounding)
__device__ __forceinline__ uint2 cvt4h(float4 v) {
    __half2 p0 = __floats2half2_rn(v.x, v.y);
    __half2 p1 = __floats2half2_rn(v.z, v.w);
    uint2 r;
    r.x = *(uint32_t*)&p0;
    r.y = *(uint32_t*)&p1;
    return r;
}

// ---------------- setup: zero stats + convert W1 (a|b) + W2 to fp16 ----------------
__global__ void setup_kernel(const float* __restrict__ W1, const float* __restrict__ W2,
                             unsigned short* __restrict__ BhA,
                             unsigned short* __restrict__ BhB,
                             unsigned short* __restrict__ Bh2,
                             double* __restrict__ stats) {
    int bid = blockIdx.x, tid = threadIdx.x;
    if (bid < 4) stats[bid * 256 + tid] = 0.0;
    if (bid < 768) {
        int idx = bid * 256 + tid;           // over 256*768
        int n = idx / 768, k = idx % 768;
        unsigned short h = __half_as_ushort(__float2half_rn(W1[idx]));
        if (k < 512) BhA[n * 512 + k] = h;
        else         BhB[n * 256 + (k - 512)] = h;
    } else {
        int idx = (bid - 768) * 256 + tid;   // over 256*256
        Bh2[idx] = __half_as_ushort(__float2half_rn(W2[idx]));
    }
}

// ---------------- 3-NN partials body (2 queries per thread) -----------------------
__device__ void three_nn_body(char* sm,
                              const float* __restrict__ xyz1,
                              const float* __restrict__ xyz2,
                              float* __restrict__ pd, int* __restrict__ pi,
                              int nb, int tid) {
    float* sx = (float*)sm;
    float* sy = sx + CHM;
    float* sz = sy + CHM;
    float* s2 = sz + CHM;
    int bx = nb & 7;               // NPTS/512 = 8
    int b  = (nb >> 3) & 15;       // batch
    int ch = nb >> 7;              // NZ chunk

    const float* p2 = xyz2 + ((size_t)b * MPTS + ch * CHM) * 3;
    {
        float px = p2[tid * 3 + 0], py = p2[tid * 3 + 1], pz = p2[tid * 3 + 2];
        sx[tid] = px; sy[tid] = py; sz[tid] = pz;
        s2[tid] = px * px + py * py + pz * pz;
    }
    __syncthreads();

    int n0 = bx * 512 + tid;
    size_t rA = (size_t)b * NPTS + n0;
    size_t rB = rA + 256;
    float ax = xyz1[rA * 3 + 0], ay = xyz1[rA * 3 + 1], az = xyz1[rA * 3 + 2];
    float bx2 = xyz1[rB * 3 + 0], by2 = xyz1[rB * 3 + 1], bz2 = xyz1[rB * 3 + 2];

    float a0 = 1e30f, a1 = 1e30f, a2 = 1e30f;
    int   ia0 = 0, ia1 = 0, ia2 = 0;
    float b0 = 1e30f, b1 = 1e30f, b2 = 1e30f;
    int   ib0 = 0, ib1 = 0, ib2 = 0;
    #pragma unroll 4
    for (int j = 0; j < CHM; j++) {
        float px = sx[j], py = sy[j], pz = sz[j], pp = s2[j];
        float dA = fmaf(-2.f, fmaf(ax, px, fmaf(ay, py, az * pz)), pp);
        float dB = fmaf(-2.f, fmaf(bx2, px, fmaf(by2, py, bz2 * pz)), pp);
        if (dA < a0)      { a2 = a1; ia2 = ia1; a1 = a0; ia1 = ia0; a0 = dA; ia0 = j; }
        else if (dA < a1) { a2 = a1; ia2 = ia1; a1 = dA; ia1 = j; }
        else if (dA < a2) { a2 = dA; ia2 = j; }
        if (dB < b0)      { b2 = b1; ib2 = ib1; b1 = b0; ib1 = ib0; b0 = dB; ib0 = j; }
        else if (dB < b1) { b2 = b1; ib2 = ib1; b1 = dB; ib1 = j; }
        else if (dB < b2) { b2 = dB; ib2 = j; }
    }
    int base = ch * CHM;
    size_t oA = ((size_t)ch * RTOT + rA) * 3;
    pd[oA + 0] = a0;  pd[oA + 1] = a1;  pd[oA + 2] = a2;
    pi[oA + 0] = base + ia0; pi[oA + 1] = base + ia1; pi[oA + 2] = base + ia2;
    size_t oB = ((size_t)ch * RTOT + rB) * 3;
    pd[oB + 0] = b0;  pd[oB + 1] = b1;  pd[oB + 2] = b2;
    pi[oB + 0] = base + ib0; pi[oB + 1] = base + ib1; pi[oB + 2] = base + ib2;
}

// ---------------- plain fp16 HMMA GEMM (1 MMA per k16), 2 CTAs/SM ------------------
// Y(M x 256) = A(M x K) * B(256 x K)^T ; A rounded once to fp16 in-kernel,
// B = W rounded to fp16. CTA 128M x 128N, 8 warps (2M x 4N), warp 64x32.
// FUSE: grid = 768; bid%3==0 -> GEMM CTA, else -> three_nn CTA.
#define RS    40
#define RSRAW 36

#define SZ_BUF   10240                // one matrix, one stage (128 * RS * 2B)
#define OFF_AHI  0                    // 2 stages -> 20480
#define OFF_BHI  20480                // 2 stages -> 20480
#define OFF_RAW  40960                // 18432
#define OFF_IDX  59392                // 1536
#define OFF_SC   60928                // 1024
#define OFF_SH   61952                // 1024
#define OFF_SUM  62976                // 1024
#define OFF_SQ   64000                // 1024
#define SM_TOTAL 65024

template<int K, int BNFIN, int GATHER, int STATS, int FUSE>
__global__ void __launch_bounds__(256, 2)
gemm_kernel(const float* __restrict__ Aptr,
            const unsigned short* __restrict__ BhG,
            const float* __restrict__ pd,
            const int* __restrict__ pi,
            const float* __restrict__ Z,
            const double* __restrict__ statsIn,
            const float* __restrict__ gvec,
            const float* __restrict__ betavec,
            float* __restrict__ Y,
            double* __restrict__ statsOut,
            const float* __restrict__ xyz1,
            const float* __restrict__ xyz2,
            float* __restrict__ pdO,
            int* __restrict__ piO) {
    constexpr int KCH = K / 32;
    extern __shared__ char sm[];
    uint32_t sb = smem_u32(sm);

    int tid = threadIdx.x, lane = tid & 31, wid = tid >> 5;
    int bid = blockIdx.x;
    int zidx;
    if (FUSE) {
        if (bid % 3 != 0) {
            three_nn_body(sm, xyz1, xyz2, pdO, piO, bid - bid / 3 - 1, tid);
            return;
        }
        zidx = bid / 3;
    } else {
        zidx = bid;
    }

    int wm = wid & 1, wn = wid >> 1;                  // 2M x 4N warps
    int rbase = (zidx >> 1) * 128;
    int nbase = (zidx & 1) * 128;

    const unsigned short* Bh = BhG + (size_t)nbase * K;

    if (GATHER) {
        if (tid < 128) {
            int r = rbase + tid;
            float d0 = 1e30f, d1 = 1e30f, d2v = 1e30f;
            int   i0 = 0, i1 = 0, i2 = 0;
            #pragma unroll
            for (int ch = 0; ch < NZ; ch++) {
                size_t o = ((size_t)ch * RTOT + r) * 3;
                #pragma unroll
                for (int k = 0; k < 3; k++) {
                    float d = pd[o + k];
                    int   ii = pi[o + k];
                    if (d < d0)        { d2v = d1; i2 = i1; d1 = d0; i1 = i0; d0 = d; i0 = ii; }
                    else if (d < d1)   { d2v = d1; i2 = i1; d1 = d;  i1 = ii; }
                    else if (d < d2v)  { d2v = d;  i2 = ii; }
                }
            }
            int* sidx = (int*)(sm + OFF_IDX);
            sidx[tid * 3 + 0] = i0;
            sidx[tid * 3 + 1] = i1;
            sidx[tid * 3 + 2] = i2;
        }
    }
    if (BNFIN) {
        double mean = statsIn[tid] * (1.0 / RTOT);
        double var  = statsIn[CO + tid] * (1.0 / RTOT) - mean * mean;
        float sc = gvec[tid] * rsqrtf((float)var + 1e-5f);
        ((float*)(sm + OFF_SC))[tid] = sc;
        ((float*)(sm + OFF_SH))[tid] = betavec[tid] - (float)mean * sc;
    }
    if (STATS) {
        ((float*)(sm + OFF_SUM))[tid] = 0.f;
        ((float*)(sm + OFF_SQ))[tid]  = 0.f;
    }
    __syncthreads();

    auto cp_chunk = [&](int c, int s) {
        int k0 = c * 32;
        #pragma unroll
        for (int it = 0; it < 2; it++) {       // B: 512 16B slots
            int slot = it * 256 + tid;
            int row = slot >> 2, q = slot & 3;
            uint32_t d = (uint32_t)(row * RS + q * 8) * 2;
            cpa16(sb + OFF_BHI + s * SZ_BUF + d, Bh + (size_t)row * K + k0 + q * 8);
        }
        #pragma unroll
        for (int it = 0; it < 4; it++) {       // A raw fp32: 1024 16B slots
            int slot = it * 256 + tid;
            int row = slot >> 3, q = slot & 7;
            uint32_t d = sb + OFF_RAW + (uint32_t)(row * RSRAW + q * 4) * 4;
            cpa16(d, Aptr + (size_t)(rbase + row) * K + k0 + q * 4);
        }
        CP_COMMIT();
    };

    auto convert_chunk = [&](int c, int s) {
        int k0 = c * 32;
        #pragma unroll
        for (int it = 0; it < 4; it++) {
            int slot = it * 256 + tid;
            int row = slot >> 3, q = slot & 7;
            float4 v = *(const float4*)(sm + OFF_RAW + (uint32_t)(row * RSRAW + q * 4) * 4);
            if (BNFIN) {
                const float* sc = (const float*)(sm + OFF_SC) + k0 + q * 4;
                const float* sh = (const float*)(sm + OFF_SH) + k0 + q * 4;
                v.x = fmaxf(v.x * sc[0] + sh[0], 0.f);
                v.y = fmaxf(v.y * sc[1] + sh[1], 0.f);
                v.z = fmaxf(v.z * sc[2] + sh[2], 0.f);
                v.w = fmaxf(v.w * sc[3] + sh[3], 0.f);
            }
            uint2 h = cvt4h(v);
            *(uint2*)(sm + OFF_AHI + s * SZ_BUF + (uint32_t)(row * RS + q * 4) * 2) = h;
        }
    };

    cp_chunk(0, 0);
    CP_WAIT0();
    convert_chunk(0, 0);
    __syncthreads();

    float acc[4][4][4] = {};   // 4 m16 x 4 n8 x 4 = 64 regs

    for (int c = 0; c < KCH; c++) {
        int s = c & 1;
        if (c + 1 < KCH) cp_chunk(c + 1, 1 - s);

        uint32_t sAhi = sb + OFF_AHI + s * SZ_BUF;
        uint32_t sBhi = sb + OFF_BHI + s * SZ_BUF;

        #pragma unroll
        for (int ks = 0; ks < 2; ks++) {
            int arow = wm * 64 + (lane & 15);
            int akoff = ks * 16 + (lane >> 4) * 8;
            int brow = wn * 32 + (lane & 7) + ((lane >> 4) & 1) * 8;
            int bkoff = ks * 16 + ((lane >> 3) & 1) * 8;

            uint32_t ah[4][4], bh[2][4];
            #pragma unroll
            for (int mi = 0; mi < 4; mi++)
                LDSM4(ah[mi], sAhi + (uint32_t)((arow + mi * 16) * RS + akoff) * 2);
            #pragma unroll
            for (int jj = 0; jj < 2; jj++)
                LDSM4(bh[jj], sBhi + (uint32_t)((brow + jj * 16) * RS + bkoff) * 2);

            #pragma unroll
            for (int mi = 0; mi < 4; mi++)
                #pragma unroll
                for (int jj = 0; jj < 2; jj++) {
                    MMA16816(acc[mi][jj * 2 + 0], ah[mi], bh[jj][0], bh[jj][1]);
                    MMA16816(acc[mi][jj * 2 + 1], ah[mi], bh[jj][2], bh[jj][3]);
                }
        }
        if (c + 1 < KCH) {
            CP_WAIT0();
            convert_chunk(c + 1, 1 - s);
        }
        __syncthreads();
    }

    // ---- epilogue ----
    if (GATHER) {
        int b = rbase >> 12;
        const float* Zb = Z + (size_t)b * MPTS * CO;
        const float third = 1.0f / 3.0f;
        const int* idxsm = (const int*)(sm + OFF_IDX);
        #pragma unroll
        for (int mi = 0; mi < 4; mi++) {
            #pragma unroll
            for (int r2 = 0; r2 < 2; r2++) {
                int lrow = wm * 64 + (lane >> 2) + mi * 16 + r2 * 8;
                const int* si = idxsm + lrow * 3;
                const float* z0 = Zb + (size_t)si[0] * CO;
                const float* z1 = Zb + (size_t)si[1] * CO;
                const float* z2 = Zb + (size_t)si[2] * CO;
                #pragma unroll
                for (int nb = 0; nb < 4; nb++) {
                    int col = nbase + wn * 32 + nb * 8 + (lane & 3) * 2;
                    float2 q0 = *(const float2*)(z0 + col);
                    float2 q1 = *(const float2*)(z1 + col);
                    float2 q2 = *(const float2*)(z2 + col);
                    acc[mi][nb][r2 * 2 + 0] += (q0.x + q1.x + q2.x) * third;
                    acc[mi][nb][r2 * 2 + 1] += (q0.y + q1.y + q2.y) * third;
                }
            }
        }
    }

    int rr = rbase + wm * 64 + (lane >> 2);
    int cc0 = nbase + wn * 32 + (lane & 3) * 2;
    #pragma unroll
    for (int mi = 0; mi < 4; mi++) {
        #pragma unroll
        for (int nb = 0; nb < 4; nb++) {
            int col = cc0 + nb * 8;
            float* a = acc[mi][nb];
            *(float2*)(Y + (size_t)(rr + mi * 16)     * CO + col) = make_float2(a[0], a[1]);
            *(float2*)(Y + (size_t)(rr + mi * 16 + 8) * CO + col) = make_float2(a[2], a[3]);
        }
    }
    if (STATS) {
        float* ssum = (float*)(sm + OFF_SUM);
        float* ssq  = (float*)(sm + OFF_SQ);
        #pragma unroll
        for (int nb = 0; nb < 4; nb++) {
            int col = cc0 + nb * 8;
            float s0 = 0.f, s1 = 0.f, q0 = 0.f, q1 = 0.f;
            #pragma unroll
            for (int mi = 0; mi < 4; mi++) {
                float* a = acc[mi][nb];
                s0 += a[0] + a[2];
                s1 += a[1] + a[3];
                q0 += a[0] * a[0] + a[2] * a[2];
                q1 += a[1] * a[1] + a[3] * a[3];
            }
            atomicAdd(&ssum[col], s0);
            atomicAdd(&ssq[col],  q0);
            atomicAdd(&ssum[col + 1], s1);
            atomicAdd(&ssq[col + 1],  q1);
        }
        __syncthreads();
        if (tid < 128) {
            int col = nbase + tid;
            atomicAdd(&statsOut[col],      (double)ssum[col]);
            atomicAdd(&statsOut[CO + col], (double)ssq[col]);
        }
    }
}

// ---------------- final BN (in-block finalize) + ReLU + transpose ------------------
__global__ void bn_relu_tr_kernel(const float* __restrict__ y,
                                  const double* __restrict__ stats,
                                  const float* __restrict__ g, const float* __restrict__ beta,
                                  float* __restrict__ out) {
    __shared__ float t[32][33];
    __shared__ float sscale[32], sshift[32];
    int b = blockIdx.z;
    int n0 = blockIdx.x * 32, c0 = blockIdx.y * 32;
    if (threadIdx.y == 0) {
        int c = c0 + threadIdx.x;
        double mean = stats[c] * (1.0 / RTOT);
        double var  = stats[CO + c] * (1.0 / RTOT) - mean * mean;
        float sc = g[c] * rsqrtf((float)var + 1e-5f);
        sscale[threadIdx.x] = sc;
        sshift[threadIdx.x] = beta[c] - (float)mean * sc;
    }
    __syncthreads();
    int n = n0 + threadIdx.y, c = c0 + threadIdx.x;
    float v = y[((size_t)b * NPTS + n) * CO + c];
    v = fmaxf(v * sscale[threadIdx.x] + sshift[threadIdx.x], 0.f);
    t[threadIdx.y][threadIdx.x] = v;
    __syncthreads();
    out[((size_t)b * CO + c0 + threadIdx.y) * NPTS + n0 + threadIdx.x] = t[threadIdx.x][threadIdx.y];
}

// ---------------- launch -----------------------------------------------------------
extern "C" void kernel_launch(void* const* d_in, const int* in_sizes, int n_in,
                              void* d_out, int out_size) {
    const float* xyz1    = (const float*)d_in[0];
    const float* xyz2    = (const float*)d_in[1];
    const float* points1 = (const float*)d_in[2];
    const float* points2 = (const float*)d_in[3];
    const float* W1      = (const float*)d_in[4];
    const float* g1      = (const float*)d_in[6];
    const float* beta1   = (const float*)d_in[7];
    const float* W2      = (const float*)d_in[8];
    const float* g2      = (const float*)d_in[10];
    const float* beta2   = (const float*)d_in[11];
    float* out = (float*)d_out;

    float *y, *y2, *Z, *pd;
    unsigned short *Bh1a, *Bh1b, *Bh2;
    int *pi;
    double* stats;
    cudaGetSymbolAddress((void**)&y, g_y);
    cudaGetSymbolAddress((void**)&y2, g_y2);
    cudaGetSymbolAddress((void**)&Z, g_Z);
    cudaGetSymbolAddress((void**)&Bh1a, g_Bh1a);
    cudaGetSymbolAddress((void**)&Bh1b, g_Bh1b);
    cudaGetSymbolAddress((void**)&Bh2, g_Bh2);
    cudaGetSymbolAddress((void**)&pd, g_pd);
    cudaGetSymbolAddress((void**)&pi, g_pi);
    cudaGetSymbolAddress((void**)&stats, g_stats);

    cudaFuncSetAttribute(gemm_kernel<512,0,0,0,1>, cudaFuncAttributeMaxDynamicSharedMemorySize, SM_TOTAL);
    cudaFuncSetAttribute(gemm_kernel<256,0,1,1,0>, cudaFuncAttributeMaxDynamicSharedMemorySize, SM_TOTAL);
    cudaFuncSetAttribute(gemm_kernel<256,1,0,1,0>, cudaFuncAttributeMaxDynamicSharedMemorySize, SM_TOTAL);

    // setup: zero stats + W1/W2 -> fp16
    setup_kernel<<<1024, 256>>>(W1, W2, Bh1a, Bh1b, Bh2, stats);

    // FUSED: Z = points2 * W1a^T  (256 GEMM CTAs) + 3-NN partials (512 CTAs)
    gemm_kernel<512,0,0,0,1><<<768, 256, SM_TOTAL>>>(
        points2, Bh1a, nullptr, nullptr, nullptr, nullptr, nullptr, nullptr,
        Z, nullptr, xyz1, xyz2, pd, pi);

    // Y1 = points1 * W1b^T + gather3(Z)/3 ; in-prologue NN merge; stats
    gemm_kernel<256,0,1,1,0><<<(RTOT / 128) * 2, 256, SM_TOTAL>>>(
        points1, Bh1b, pd, pi, Z, nullptr, nullptr, nullptr, y, stats,
        nullptr, nullptr, nullptr, nullptr);

    // Y2 = relu(bn(Y1)) * W2^T ; in-prologue finalize from stats1 ; stats
    gemm_kernel<256,1,0,1,0><<<(RTOT / 128) * 2, 256, SM_TOTAL>>>(
        y, Bh2, nullptr, nullptr, nullptr, stats, g1, beta1, y2, stats + 512,
        nullptr, nullptr, nullptr, nullptr);

    // final BN (in-block finalize from stats2) + ReLU + transpose
    bn_relu_tr_kernel<<<dim3(NPTS / 32, CO / 32, BATCH), dim3(32, 32)>>>(
        y2, stats + 512, g2, beta2, out);
}

// round 17
// speedup vs baseline: 1.1674x; 1.0073x over previous
#include <cuda_runtime.h>
#include <cuda_fp16.h>
#include <cstdint>

// Problem constants
#define BATCH 16
#define NPTS  4096
#define MPTS  1024
#define C1    256
#define C2    512
#define CO    256
#define RTOT  65536
#define NZ    4
#define CHM   (MPTS / NZ)   // 256

// ---------------- scratch (static __device__ globals; no allocation) ----------
__device__ float  g_y  [(size_t)RTOT * CO];
__device__ float  g_y2 [(size_t)RTOT * CO];
__device__ float  g_Z  [(size_t)BATCH * MPTS * CO];     // P2 * W1a^T
__device__ unsigned short g_Bh1a[CO * 512];
__device__ unsigned short g_Bh1b[CO * 256];
__device__ unsigned short g_Bh2 [CO * 256];
__device__ float  g_pd [(size_t)NZ * RTOT * 3];
__device__ int    g_pi [(size_t)NZ * RTOT * 3];
__device__ double g_stats[1024];

// ---------------- helpers ---------------------------------------------------------
__device__ __forceinline__ uint32_t smem_u32(const void* p) {
    uint32_t a;
    asm("{ .reg .u64 t; cvta.to.shared.u64 t, %1; cvt.u32.u64 %0, t; }" : "=r"(a) : "l"(p));
    return a;
}

__device__ __forceinline__ void cpa16(uint32_t s, const void* g) {
    asm volatile("cp.async.cg.shared.global [%0], [%1], 16;" :: "r"(s), "l"(g));
}
#define CP_COMMIT() asm volatile("cp.async.commit_group;" ::: "memory")
#define CP_WAIT0()  asm volatile("cp.async.wait_group 0;" ::: "memory")

#define LDSM4(r, addr) \
    asm volatile("ldmatrix.sync.aligned.m8n8.x4.shared.b16 {%0,%1,%2,%3}, [%4];" \
                 : "=r"((r)[0]), "=r"((r)[1]), "=r"((r)[2]), "=r"((r)[3]) : "r"(addr))

#define MMA16816(d, a, b0, b1) \
    asm volatile("mma.sync.aligned.m16n8k16.row.col.f32.f16.f16.f32 " \
                 "{%0,%1,%2,%3}, {%4,%5,%6,%7}, {%8,%9}, {%0,%1,%2,%3};" \
                 : "+f"((d)[0]), "+f"((d)[1]), "+f"((d)[2]), "+f"((d)[3]) \
                 : "r"((a)[0]), "r"((a)[1]), "r"((a)[2]), "r"((a)[3]), "r"(b0), "r"(b1))

// fp32x4 -> fp16x4 (single rounding)
__device__ __forceinline__ uint2 cvt4h(float4 v) {
    __half2 p0 = __floats2half2_rn(v.x, v.y);
    __half2 p1 = __floats2half2_rn(v.z, v.w);
    uint2 r;
    r.x = *(uint32_t*)&p0;
    r.y = *(uint32_t*)&p1;
    return r;
}

// ---------------- setup: zero stats + convert W1 (a|b) + W2 to fp16 ----------------
__global__ void setup_kernel(const float* __restrict__ W1, const float* __restrict__ W2,
                             unsigned short* __restrict__ BhA,
                             unsigned short* __restrict__ BhB,
                             unsigned short* __restrict__ Bh2,
                             double* __restrict__ stats) {
    int bid = blockIdx.x, tid = threadIdx.x;
    if (bid < 4) stats[bid * 256 + tid] = 0.0;
    if (bid < 768) {
        int idx = bid * 256 + tid;           // over 256*768
        int n = idx / 768, k = idx % 768;
        unsigned short h = __half_as_ushort(__float2half_rn(W1[idx]));
        if (k < 512) BhA[n * 512 + k] = h;
        else         BhB[n * 256 + (k - 512)] = h;
    } else {
        int idx = (bid - 768) * 256 + tid;   // over 256*256
        Bh2[idx] = __half_as_ushort(__float2half_rn(W2[idx]));
    }
}

// ---------------- 3-NN partials body (2 queries per thread) -----------------------
__device__ void three_nn_body(char* sm,
                              const float* __restrict__ xyz1,
                              const float* __restrict__ xyz2,
                              float* __restrict__ pd, int* __restrict__ pi,
                              int nb, int tid) {
    float* sx = (float*)sm;
    float* sy = sx + CHM;
    float* sz = sy + CHM;
    float* s2 = sz + CHM;
    int bx = nb & 7;               // NPTS/512 = 8
    int b  = (nb >> 3) & 15;       // batch
    int ch = nb >> 7;              // NZ chunk

    const float* p2 = xyz2 + ((size_t)b * MPTS + ch * CHM) * 3;
    {
        float px = p2[tid * 3 + 0], py = p2[tid * 3 + 1], pz = p2[tid * 3 + 2];
        sx[tid] = px; sy[tid] = py; sz[tid] = pz;
        s2[tid] = px * px + py * py + pz * pz;
    }
    __syncthreads();

    int n0 = bx * 512 + tid;
    size_t rA = (size_t)b * NPTS + n0;
    size_t rB = rA + 256;
    float ax = xyz1[rA * 3 + 0], ay = xyz1[rA * 3 + 1], az = xyz1[rA * 3 + 2];
    float bx2 = xyz1[rB * 3 + 0], by2 = xyz1[rB * 3 + 1], bz2 = xyz1[rB * 3 + 2];

    float a0 = 1e30f, a1 = 1e30f, a2 = 1e30f;
    int   ia0 = 0, ia1 = 0, ia2 = 0;
    float b0 = 1e30f, b1 = 1e30f, b2 = 1e30f;
    int   ib0 = 0, ib1 = 0, ib2 = 0;
    #pragma unroll 4
    for (int j = 0; j < CHM; j++) {
        float px = sx[j], py = sy[j], pz = sz[j], pp = s2[j];
        float dA = fmaf(-2.f, fmaf(ax, px, fmaf(ay, py, az * pz)), pp);
        float dB = fmaf(-2.f, fmaf(bx2, px, fmaf(by2, py, bz2 * pz)), pp);
        if (dA < a0)      { a2 = a1; ia2 = ia1; a1 = a0; ia1 = ia0; a0 = dA; ia0 = j; }
        else if (dA < a1) { a2 = a1; ia2 = ia1; a1 = dA; ia1 = j; }
        else if (dA < a2) { a2 = dA; ia2 = j; }
        if (dB < b0)      { b2 = b1; ib2 = ib1; b1 = b0; ib1 = ib0; b0 = dB; ib0 = j; }
        else if (dB < b1) { b2 = b1; ib2 = ib1; b1 = dB; ib1 = j; }
        else if (dB < b2) { b2 = dB; ib2 = j; }
    }
    int base = ch * CHM;
    size_t oA = ((size_t)ch * RTOT + rA) * 3;
    pd[oA + 0] = a0;  pd[oA + 1] = a1;  pd[oA + 2] = a2;
    pi[oA + 0] = base + ia0; pi[oA + 1] = base + ia1; pi[oA + 2] = base + ia2;
    size_t oB = ((size_t)ch * RTOT + rB) * 3;
    pd[oB + 0] = b0;  pd[oB + 1] = b1;  pd[oB + 2] = b2;
    pi[oB + 0] = base + ib0; pi[oB + 1] = base + ib1; pi[oB + 2] = base + ib2;
}

// ---------------- plain fp16 HMMA GEMM, K-chunk = 64, 2 CTAs/SM --------------------
// Y(M x 256) = A(M x K) * B(256 x K)^T ; A rounded once to fp16 in-kernel,
// B = W rounded to fp16. CTA 128M x 128N, 8 warps (2M x 4N), warp 64x32.
// FUSE: grid = 768; bid%3==0 -> GEMM CTA, else -> three_nn CTA.
#define RS    72      // fp16 smem row stride (64 + 8 pad) -> 144B rows
#define RSRAW 68      // raw fp32 staging row stride (64 + 4 pad) -> 272B, 16B-aligned

#define SZ_STG   18432                // one matrix, one stage (128 * RS * 2B)
#define OFF_A    0                    // 2 stages -> 36864
#define OFF_B    36864                // 2 stages -> 36864
#define OFF_RAW  73728                // 34816 (dead by epilogue)
#define OFF_SUM  73728                // overlays RAW (epilogue only)
#define OFF_SQ   74752                // overlays RAW (epilogue only)
#define OFF_EXT  108544               // 2048: IDX (gather) or SC+SH (bnfin)
#define SM_TOTAL 110592

template<int K, int BNFIN, int GATHER, int STATS, int FUSE>
__global__ void __launch_bounds__(256, 2)
gemm_kernel(const float* __restrict__ Aptr,
            const unsigned short* __restrict__ BhG,
            const float* __restrict__ pd,
            const int* __restrict__ pi,
            const float* __restrict__ Z,
            const double* __restrict__ statsIn,
            const float* __restrict__ gvec,
            const float* __restrict__ betavec,
            float* __restrict__ Y,
            double* __restrict__ statsOut,
            const float* __restrict__ xyz1,
            const float* __restrict__ xyz2,
            float* __restrict__ pdO,
            int* __restrict__ piO) {
    constexpr int KCH = K / 64;
    extern __shared__ char sm[];
    uint32_t sb = smem_u32(sm);

    int tid = threadIdx.x, lane = tid & 31, wid = tid >> 5;
    int bid = blockIdx.x;
    int zidx;
    if (FUSE) {
        if (bid % 3 != 0) {
            three_nn_body(sm, xyz1, xyz2, pdO, piO, bid - bid / 3 - 1, tid);
            return;
        }
        zidx = bid / 3;
    } else {
        zidx = bid;
    }

    int wm = wid & 1, wn = wid >> 1;                  // 2M x 4N warps
    int rbase = (zidx >> 1) * 128;
    int nbase = (zidx & 1) * 128;

    const unsigned short* Bh = BhG + (size_t)nbase * K;

    if (GATHER) {
        if (tid < 128) {
            int r = rbase + tid;
            float d0 = 1e30f, d1 = 1e30f, d2v = 1e30f;
            int   i0 = 0, i1 = 0, i2 = 0;
            #pragma unroll
            for (int ch = 0; ch < NZ; ch++) {
                size_t o = ((size_t)ch * RTOT + r) * 3;
                #pragma unroll
                for (int k = 0; k < 3; k++) {
                    float d = pd[o + k];
                    int   ii = pi[o + k];
                    if (d < d0)        { d2v = d1; i2 = i1; d1 = d0; i1 = i0; d0 = d; i0 = ii; }
                    else if (d < d1)   { d2v = d1; i2 = i1; d1 = d;  i1 = ii; }
                    else if (d < d2v)  { d2v = d;  i2 = ii; }
                }
            }
            int* sidx = (int*)(sm + OFF_EXT);
            sidx[tid * 3 + 0] = i0;
            sidx[tid * 3 + 1] = i1;
            sidx[tid * 3 + 2] = i2;
        }
    }
    if (BNFIN) {
        double mean = statsIn[tid] * (1.0 / RTOT);
        double var  = statsIn[CO + tid] * (1.0 / RTOT) - mean * mean;
        float sc = gvec[tid] * rsqrtf((float)var + 1e-5f);
        ((float*)(sm + OFF_EXT))[tid] = sc;
        ((float*)(sm + OFF_EXT + 1024))[tid] = betavec[tid] - (float)mean * sc;
    }
    __syncthreads();

    // Per chunk (64 cols): B = 1024 16B slots (4/thread), A raw = 2048 slots (8/thread)
    auto cp_chunk = [&](int c, int s) {
        int k0 = c * 64;
        #pragma unroll
        for (int it = 0; it < 4; it++) {
            int slot = it * 256 + tid;
            int row = slot >> 3, q = slot & 7;
            uint32_t d = sb + OFF_B + s * SZ_STG + (uint32_t)(row * RS + q * 8) * 2;
            cpa16(d, Bh + (size_t)row * K + k0 + q * 8);
        }
        #pragma unroll
        for (int it = 0; it < 8; it++) {
            int slot = it * 256 + tid;
            int row = slot >> 4, q = slot & 15;
            uint32_t d = sb + OFF_RAW + (uint32_t)(row * RSRAW + q * 4) * 4;
            cpa16(d, Aptr + (size_t)(rbase + row) * K + k0 + q * 4);
        }
        CP_COMMIT();
    };

    auto convert_chunk = [&](int c, int s) {
        int k0 = c * 64;
        #pragma unroll
        for (int it = 0; it < 8; it++) {
            int slot = it * 256 + tid;
            int row = slot >> 4, q = slot & 15;
            float4 v = *(const float4*)(sm + OFF_RAW + (uint32_t)(row * RSRAW + q * 4) * 4);
            if (BNFIN) {
                const float* sc = (const float*)(sm + OFF_EXT) + k0 + q * 4;
                const float* sh = (const float*)(sm + OFF_EXT + 1024) + k0 + q * 4;
                v.x = fmaxf(v.x * sc[0] + sh[0], 0.f);
                v.y = fmaxf(v.y * sc[1] + sh[1], 0.f);
                v.z = fmaxf(v.z * sc[2] + sh[2], 0.f);
                v.w = fmaxf(v.w * sc[3] + sh[3], 0.f);
            }
            uint2 h = cvt4h(v);
            *(uint2*)(sm + OFF_A + s * SZ_STG + (uint32_t)(row * RS + q * 4) * 2) = h;
        }
    };

    cp_chunk(0, 0);
    CP_WAIT0();
    convert_chunk(0, 0);
    __syncthreads();

    float acc[4][4][4] = {};   // 4 m16 x 4 n8 x 4 = 64 regs

    for (int c = 0; c < KCH; c++) {
        int s = c & 1;
        if (c + 1 < KCH) cp_chunk(c + 1, 1 - s);

        uint32_t sA = sb + OFF_A + s * SZ_STG;
        uint32_t sB = sb + OFF_B + s * SZ_STG;

        #pragma unroll
        for (int ks = 0; ks < 4; ks++) {
            int arow = wm * 64 + (lane & 15);
            int akoff = ks * 16 + (lane >> 4) * 8;
            int brow = wn * 32 + (lane & 7) + ((lane >> 4) & 1) * 8;
            int bkoff = ks * 16 + ((lane >> 3) & 1) * 8;

            uint32_t ah[4][4], bh[2][4];
            #pragma unroll
            for (int mi = 0; mi < 4; mi++)
                LDSM4(ah[mi], sA + (uint32_t)((arow + mi * 16) * RS + akoff) * 2);
            #pragma unroll
            for (int jj = 0; jj < 2; jj++)
                LDSM4(bh[jj], sB + (uint32_t)((brow + jj * 16) * RS + bkoff) * 2);

            #pragma unroll
            for (int mi = 0; mi < 4; mi++)
                #pragma unroll
                for (int jj = 0; jj < 2; jj++) {
                    MMA16816(acc[mi][jj * 2 + 0], ah[mi], bh[jj][0], bh[jj][1]);
                    MMA16816(acc[mi][jj * 2 + 1], ah[mi], bh[jj][2], bh[jj][3]);
                }
        }
        if (c + 1 < KCH) {
            CP_WAIT0();
            convert_chunk(c + 1, 1 - s);
        }
        __syncthreads();
    }

    // ---- epilogue ----
    if (GATHER) {
        int b = rbase >> 12;
        const float* Zb = Z + (size_t)b * MPTS * CO;
        const float third = 1.0f / 3.0f;
        const int* idxsm = (const int*)(sm + OFF_EXT);
        #pragma unroll
        for (int mi = 0; mi < 4; mi++) {
            #pragma unroll
            for (int r2 = 0; r2 < 2; r2++) {
                int lrow = wm * 64 + (lane >> 2) + mi * 16 + r2 * 8;
                const int* si = idxsm + lrow * 3;
                const float* z0 = Zb + (size_t)si[0] * CO;
                const float* z1 = Zb + (size_t)si[1] * CO;
                const float* z2 = Zb + (size_t)si[2] * CO;
                #pragma unroll
                for (int nb = 0; nb < 4; nb++) {
                    int col = nbase + wn * 32 + nb * 8 + (lane & 3) * 2;
                    float2 q0 = *(const float2*)(z0 + col);
                    float2 q1 = *(const float2*)(z1 + col);
                    float2 q2 = *(const float2*)(z2 + col);
                    acc[mi][nb][r2 * 2 + 0] += (q0.x + q1.x + q2.x) * third;
                    acc[mi][nb][r2 * 2 + 1] += (q0.y + q1.y + q2.y) * third;
                }
            }
        }
    }

    int rr = rbase + wm * 64 + (lane >> 2);
    int cc0 = nbase + wn * 32 + (lane & 3) * 2;
    #pragma unroll
    for (int mi = 0; mi < 4; mi++) {
        #pragma unroll
        for (int nb = 0; nb < 4; nb++) {
            int col = cc0 + nb * 8;
            float* a = acc[mi][nb];
            *(float2*)(Y + (size_t)(rr + mi * 16)     * CO + col) = make_float2(a[0], a[1]);
            *(float2*)(Y + (size_t)(rr + mi * 16 + 8) * CO + col) = make_float2(a[2], a[3]);
        }
    }
    if (STATS) {
        // SUM/SQ overlay the (now dead) RAW staging region; zero here, then reduce.
        float* ssum = (float*)(sm + OFF_SUM);
        float* ssq  = (float*)(sm + OFF_SQ);
        ssum[tid] = 0.f;
        ssq[tid]  = 0.f;
        __syncthreads();
        #pragma unroll
        for (int nb = 0; nb < 4; nb++) {
            int col = cc0 + nb * 8;
            float s0 = 0.f, s1 = 0.f, q0 = 0.f, q1 = 0.f;
            #pragma unroll
            for (int mi = 0; mi < 4; mi++) {
                float* a = acc[mi][nb];
                s0 += a[0] + a[2];
                s1 += a[1] + a[3];
                q0 += a[0] * a[0] + a[2] * a[2];
                q1 += a[1] * a[1] + a[3] * a[3];
            }
            atomicAdd(&ssum[col], s0);
            atomicAdd(&ssq[col],  q0);
            atomicAdd(&ssum[col + 1], s1);
            atomicAdd(&ssq[col + 1],  q1);
        }
        __syncthreads();
        if (tid < 128) {
            int col = nbase + tid;
            atomicAdd(&statsOut[col],      (double)ssum[col]);
            atomicAdd(&statsOut[CO + col], (double)ssq[col]);
        }
    }
}

// ---------------- final BN (in-block finalize) + ReLU + transpose ------------------
__global__ void bn_relu_tr_kernel(const float* __restrict__ y,
                                  const double* __restrict__ stats,
                                  const float* __restrict__ g, const float* __restrict__ beta,
                                  float* __restrict__ out) {
    __shared__ float t[32][33];
    __shared__ float sscale[32], sshift[32];
    int b = blockIdx.z;
    int n0 = blockIdx.x * 32, c0 = blockIdx.y * 32;
    if (threadIdx.y == 0) {
        int c = c0 + threadIdx.x;
        double mean = stats[c] * (1.0 / RTOT);
        double var  = stats[CO + c] * (1.0 / RTOT) - mean * mean;
        float sc = g[c] * rsqrtf((float)var + 1e-5f);
        sscale[threadIdx.x] = sc;
        sshift[threadIdx.x] = beta[c] - (float)mean * sc;
    }
    __syncthreads();
    int n = n0 + threadIdx.y, c = c0 + threadIdx.x;
    float v = y[((size_t)b * NPTS + n) * CO + c];
    v = fmaxf(v * sscale[threadIdx.x] + sshift[threadIdx.x], 0.f);
    t[threadIdx.y][threadIdx.x] = v;
    __syncthreads();
    out[((size_t)b * CO + c0 + threadIdx.y) * NPTS + n0 + threadIdx.x] = t[threadIdx.x][threadIdx.y];
}

// ---------------- launch -----------------------------------------------------------
extern "C" void kernel_launch(void* const* d_in, const int* in_sizes, int n_in,
                              void* d_out, int out_size) {
    const float* xyz1    = (const float*)d_in[0];
    const float* xyz2    = (const float*)d_in[1];
    const float* points1 = (const float*)d_in[2];
    const float* points2 = (const float*)d_in[3];
    const float* W1      = (const float*)d_in[4];
    const float* g1      = (const float*)d_in[6];
    const float* beta1   = (const float*)d_in[7];
    const float* W2      = (const float*)d_in[8];
    const float* g2      = (const float*)d_in[10];
    const float* beta2   = (const float*)d_in[11];
    float* out = (float*)d_out;

    float *y, *y2, *Z, *pd;
    unsigned short *Bh1a, *Bh1b, *Bh2;
    int *pi;
    double* stats;
    cudaGetSymbolAddress((void**)&y, g_y);
    cudaGetSymbolAddress((void**)&y2, g_y2);
    cudaGetSymbolAddress((void**)&Z, g_Z);
    cudaGetSymbolAddress((void**)&Bh1a, g_Bh1a);
    cudaGetSymbolAddress((void**)&Bh1b, g_Bh1b);
    cudaGetSymbolAddress((void**)&Bh2, g_Bh2);
    cudaGetSymbolAddress((void**)&pd, g_pd);
    cudaGetSymbolAddress((void**)&pi, g_pi);
    cudaGetSymbolAddress((void**)&stats, g_stats);

    cudaFuncSetAttribute(gemm_kernel<512,0,0,0,1>, cudaFuncAttributeMaxDynamicSharedMemorySize, SM_TOTAL);
    cudaFuncSetAttribute(gemm_kernel<256,0,1,1,0>, cudaFuncAttributeMaxDynamicSharedMemorySize, SM_TOTAL);
    cudaFuncSetAttribute(gemm_kernel<256,1,0,1,0>, cudaFuncAttributeMaxDynamicSharedMemorySize, SM_TOTAL);

    // setup: zero stats + W1/W2 -> fp16
    setup_kernel<<<1024, 256>>>(W1, W2, Bh1a, Bh1b, Bh2, stats);

    // FUSED: Z = points2 * W1a^T  (256 GEMM CTAs) + 3-NN partials (512 CTAs)
    gemm_kernel<512,0,0,0,1><<<768, 256, SM_TOTAL>>>(
        points2, Bh1a, nullptr, nullptr, nullptr, nullptr, nullptr, nullptr,
        Z, nullptr, xyz1, xyz2, pd, pi);

    // Y1 = points1 * W1b^T + gather3(Z)/3 ; in-prologue NN merge; stats
    gemm_kernel<256,0,1,1,0><<<(RTOT / 128) * 2, 256, SM_TOTAL>>>(
        points1, Bh1b, pd, pi, Z, nullptr, nullptr, nullptr, y, stats,
        nullptr, nullptr, nullptr, nullptr);

    // Y2 = relu(bn(Y1)) * W2^T ; in-prologue finalize from stats1 ; stats
    gemm_kernel<256,1,0,1,0><<<(RTOT / 128) * 2, 256, SM_TOTAL>>>(
        y, Bh2, nullptr, nullptr, nullptr, stats, g1, beta1, y2, stats + 512,
        nullptr, nullptr, nullptr, nullptr);

    // final BN (in-block finalize from stats2) + ReLU + transpose
    bn_relu_tr_kernel<<<dim3(NPTS / 32, CO / 32, BATCH), dim3(32, 32)>>>(
        y2, stats + 512, g2, beta2, out);
}